// round 11
// baseline (speedup 1.0000x reference)
#include <cuda_runtime.h>
#include <cuda_bf16.h>
#include <math.h>
#include <stdint.h>

// Problem constants
#define BB 2
#define TT 2048
#define CC 1024
#define HH 16
#define HD 64
#define M_ROWS (BB*TT)        // 4096
#define QKV_N  (3*CC)         // 3072
#define K3     (3*CC)         // augmented K = 3072

// ---------------------------------------------------------------------------
// Scratch (__device__ globals; no cudaMalloc allowed)
// ---------------------------------------------------------------------------
__device__ __nv_bfloat16 g_xs [(size_t)M_ROWS * K3];
__device__ __nv_bfloat16 g_ys [(size_t)M_ROWS * K3];
__device__ __nv_bfloat16 g_wqs[(size_t)QKV_N * K3];
__device__ __nv_bfloat16 g_wos[(size_t)CC * K3];
#define HSZ ((size_t)BB * HH * TT * HD)
__device__ __nv_bfloat16 g_qh[HSZ];
__device__ __nv_bfloat16 g_ql[HSZ];
__device__ __nv_bfloat16 g_kh[HSZ];
__device__ __nv_bfloat16 g_kl[HSZ];
__device__ __nv_bfloat16 g_vh[HSZ];
__device__ __nv_bfloat16 g_vl[HSZ];

// ---------------------------------------------------------------------------
// PTX helpers
// ---------------------------------------------------------------------------
__device__ __forceinline__ uint32_t smem_u32(const void* p) {
    uint32_t a;
    asm("{ .reg .u64 t; cvta.to.shared.u64 t, %1; cvt.u32.u64 %0, t; }" : "=r"(a) : "l"(p));
    return a;
}
__device__ __forceinline__ void cp16(uint32_t dst, const void* src) {
    asm volatile("cp.async.cg.shared.global [%0], [%1], 16;" :: "r"(dst), "l"(src));
}
#define CP_COMMIT() asm volatile("cp.async.commit_group;" ::: "memory")
#define CP_WAIT(n)  asm volatile("cp.async.wait_group %0;" :: "n"(n) : "memory")

__device__ __forceinline__ void ldsm4(uint32_t* r, uint32_t addr) {
    asm volatile("ldmatrix.sync.aligned.m8n8.x4.shared.b16 {%0,%1,%2,%3}, [%4];"
        : "=r"(r[0]), "=r"(r[1]), "=r"(r[2]), "=r"(r[3]) : "r"(addr));
}
__device__ __forceinline__ void ldsm4t(uint32_t* r, uint32_t addr) {
    asm volatile("ldmatrix.sync.aligned.m8n8.x4.trans.shared.b16 {%0,%1,%2,%3}, [%4];"
        : "=r"(r[0]), "=r"(r[1]), "=r"(r[2]), "=r"(r[3]) : "r"(addr));
}
__device__ __forceinline__ void mma16816(float* d, const uint32_t* a, const uint32_t* b) {
    asm volatile(
        "mma.sync.aligned.m16n8k16.row.col.f32.bf16.bf16.f32 "
        "{%0,%1,%2,%3}, {%4,%5,%6,%7}, {%8,%9}, {%0,%1,%2,%3};"
        : "+f"(d[0]), "+f"(d[1]), "+f"(d[2]), "+f"(d[3])
        : "r"(a[0]), "r"(a[1]), "r"(a[2]), "r"(a[3]), "r"(b[0]), "r"(b[1]));
}
__device__ __forceinline__ uint32_t pack_bf16x2(__nv_bfloat16 a, __nv_bfloat16 b) {
    __nv_bfloat162 h = __halves2bfloat162(a, b);
    return *reinterpret_cast<uint32_t*>(&h);
}
__device__ __forceinline__ void split1(float v, __nv_bfloat16& h, __nv_bfloat16& l) {
    h = __float2bfloat16(v);
    l = __float2bfloat16(v - __bfloat162float(h));
}

// ---------------------------------------------------------------------------
// Conversion kernels for the GEMM inputs
// ---------------------------------------------------------------------------
__global__ void split3_act(const float* __restrict__ in,
                           __nv_bfloat16* __restrict__ out, int n4)
{
    int i = blockIdx.x * blockDim.x + threadIdx.x;
    if (i >= n4) return;
    int m  = i >> 8;
    int kc = i & 255;
    float4 v = reinterpret_cast<const float4*>(in)[i];
    __nv_bfloat16 h[4], l[4];
    float f[4] = {v.x, v.y, v.z, v.w};
#pragma unroll
    for (int j = 0; j < 4; j++) split1(f[j], h[j], l[j]);
    __nv_bfloat162 hp0(h[0], h[1]), hp1(h[2], h[3]);
    __nv_bfloat162 lp0(l[0], l[1]), lp1(l[2], l[3]);
    __nv_bfloat162* o = reinterpret_cast<__nv_bfloat162*>(out + (size_t)m * K3 + kc * 4);
    o[0] = hp0; o[1] = hp1;
    o[CC / 2 + 0] = hp0; o[CC / 2 + 1] = hp1;
    o[CC + 0] = lp0; o[CC + 1] = lp1;
}

__global__ __launch_bounds__(256) void tsplit3(
    const float* __restrict__ W, int N, __nv_bfloat16* __restrict__ out)
{
    __shared__ float t[32][33];
    const int nb = blockIdx.x * 32;
    const int kb = blockIdx.y * 32;
    const int tx = threadIdx.x & 31;
    const int ty = threadIdx.x >> 5;
    for (int r = ty; r < 32; r += 8)
        t[r][tx] = W[(size_t)(kb + r) * N + nb + tx];
    __syncthreads();
    for (int r = ty; r < 32; r += 8) {
        float v = t[tx][r];
        __nv_bfloat16 h, l;
        split1(v, h, l);
        size_t o = (size_t)(nb + r) * K3 + kb + tx;
        out[o]          = h;
        out[o + CC]     = l;
        out[o + 2 * CC] = h;
    }
}

// ---------------------------------------------------------------------------
// bf16 HMMA GEMM (R8 loop structure + R9 hoisted addressing)
// ---------------------------------------------------------------------------
#define GATILE 16384             // 128 rows * 128 B
#define GSTAGE (2 * GATILE)      // 32768 (A + B)
#define GEMM_SMEM (3 * GSTAGE)   // 98304
#define NKB (K3 / 64)            // 48

template <int MODE>
__global__ __launch_bounds__(256) void gemm_mma(
    int N,
    const __nv_bfloat16* __restrict__ A,
    const __nv_bfloat16* __restrict__ B,
    const float* __restrict__ bias,
    float* __restrict__ C,
    __nv_bfloat16* __restrict__ qh, __nv_bfloat16* __restrict__ ql,
    __nv_bfloat16* __restrict__ kh, __nv_bfloat16* __restrict__ kl,
    __nv_bfloat16* __restrict__ vh, __nv_bfloat16* __restrict__ vl)
{
    extern __shared__ char smem[];
    const uint32_t sbase = smem_u32(smem);

    const int tid  = threadIdx.x;
    const int lane = tid & 31;
    const int wid  = tid >> 5;
    const int wm   = wid >> 2;
    const int wn   = wid & 3;
    const int m0   = blockIdx.y * 128;
    const int n0   = blockIdx.x * 128;

    const int lr = tid >> 3;           // 0..31
    const int lc = tid & 7;            // 0..7
    const uint32_t stoff = (uint32_t)(lr * 128 + ((lc ^ (lr & 7)) * 16));
    const __nv_bfloat16* pA = A + (size_t)(m0 + lr) * K3 + lc * 8;
    const __nv_bfloat16* pB = B + (size_t)(n0 + lr) * K3 + lc * 8;

    float acc[4][4][4];
#pragma unroll
    for (int mi = 0; mi < 4; mi++)
#pragma unroll
        for (int nj = 0; nj < 4; nj++)
#pragma unroll
            for (int r = 0; r < 4; r++) acc[mi][nj][r] = 0.0f;

    auto load_stage = [&](int kb, int st) {
        const uint32_t sa  = sbase + st * GSTAGE;
        const uint32_t sbm = sa + GATILE;
        const int k0 = kb * 64;
#pragma unroll
        for (int j = 0; j < 4; j++)
            cp16(sa + stoff + j * 4096, pA + (size_t)j * 32 * K3 + k0);
#pragma unroll
        for (int j = 0; j < 4; j++)
            cp16(sbm + stoff + j * 4096, pB + (size_t)j * 32 * K3 + k0);
        CP_COMMIT();
    };

    uint32_t rowA[4], uA[4], rowB[2], uB[4];
#pragma unroll
    for (int mi = 0; mi < 4; mi++)
        rowA[mi] = (uint32_t)((wm * 64 + mi * 16 + (lane & 15)) * 128);
#pragma unroll
    for (int ks = 0; ks < 4; ks++)
        uA[ks] = (uint32_t)((((ks * 2 + (lane >> 4)) ^ (lane & 7)) * 16));
#pragma unroll
    for (int nj2 = 0; nj2 < 2; nj2++)
        rowB[nj2] = (uint32_t)((wn * 32 + nj2 * 16 + (lane & 7) + (((lane >> 4) & 1) * 8)) * 128);
#pragma unroll
    for (int ks = 0; ks < 4; ks++)
        uB[ks] = (uint32_t)((((ks * 2 + ((lane >> 3) & 1)) ^ (lane & 7)) * 16));

    load_stage(0, 0);
    load_stage(1, 1);

    for (int kb = 0; kb < NKB; kb++) {
        const int st = kb % 3;
        if (kb + 2 < NKB) {
            load_stage(kb + 2, (kb + 2) % 3);
            CP_WAIT(2);
        } else if (kb + 1 < NKB) {
            CP_WAIT(1);
        } else {
            CP_WAIT(0);
        }
        __syncthreads();

        const uint32_t sa  = sbase + st * GSTAGE;
        const uint32_t sbm = sa + GATILE;

#pragma unroll
        for (int ks = 0; ks < 4; ks++) {
            uint32_t af[4][4];
#pragma unroll
            for (int mi = 0; mi < 4; mi++)
                ldsm4(af[mi], sa + rowA[mi] + uA[ks]);
            uint32_t bf[2][4];
#pragma unroll
            for (int nj2 = 0; nj2 < 2; nj2++)
                ldsm4(bf[nj2], sbm + rowB[nj2] + uB[ks]);
#pragma unroll
            for (int mi = 0; mi < 4; mi++)
#pragma unroll
                for (int nj = 0; nj < 4; nj++)
                    mma16816(acc[mi][nj], af[mi], &bf[nj >> 1][(nj & 1) * 2]);
        }
        __syncthreads();
    }

    // Epilogue
#pragma unroll
    for (int mi = 0; mi < 4; mi++) {
#pragma unroll
        for (int nj = 0; nj < 4; nj++) {
            const int row = m0 + wm * 64 + mi * 16 + (lane >> 2);
            const int col = n0 + wn * 32 + nj * 8 + 2 * (lane & 3);
            float2 bz = *reinterpret_cast<const float2*>(bias + col);
            float2 v0 = make_float2(acc[mi][nj][0] + bz.x, acc[mi][nj][1] + bz.y);
            float2 v1 = make_float2(acc[mi][nj][2] + bz.x, acc[mi][nj][3] + bz.y);
            if (MODE == 0) {
                *reinterpret_cast<float2*>(C + (size_t)row * N + col) = v0;
                *reinterpret_cast<float2*>(C + (size_t)(row + 8) * N + col) = v1;
            } else {
                const int seg = col >> 10;
                const int hc  = col & 1023;
                const int h   = hc >> 6;
                const int d   = hc & 63;
                if (seg == 0) { v0.x *= 0.125f; v0.y *= 0.125f; v1.x *= 0.125f; v1.y *= 0.125f; }
                __nv_bfloat16* hp = (seg == 0) ? qh : (seg == 1) ? kh : vh;
                __nv_bfloat16* lp = (seg == 0) ? ql : (seg == 1) ? kl : vl;
#pragma unroll
                for (int rr = 0; rr < 2; rr++) {
                    const int m = row + rr * 8;
                    const int b = m >> 11, t = m & 2047;
                    const size_t dst = (((size_t)(b * HH + h)) * TT + t) * HD + d;
                    float2 v = rr ? v1 : v0;
                    __nv_bfloat16 h0, l0, h1, l1;
                    split1(v.x, h0, l0);
                    split1(v.y, h1, l1);
                    *reinterpret_cast<uint32_t*>(hp + dst) = pack_bf16x2(h0, h1);
                    *reinterpret_cast<uint32_t*>(lp + dst) = pack_bf16x2(l0, l1);
                }
            }
        }
    }
}

// ---------------------------------------------------------------------------
// Flash attention on HMMA, split-bf16 (3-term), BQ=128 (8 warps, 256 thr).
// KV tiles of 64 double-buffered; per-warp skip of fully-masked tiles.
// Epilogue writes split3 rows of y directly: [yh | yh | yl].
// ---------------------------------------------------------------------------
#define AP 144
#define KTILE_B (64 * AP)            // 9216
#define Q_H 0
#define Q_L (128 * AP)               // Q hi: 128 rows
#define QSTG (2 * 128 * AP)          // 36864
#define KV_STAGE (4 * KTILE_B)       // 36864
#define ATTN_SMEM (QSTG + 2 * KV_STAGE)  // 110592
#define NQT (TT / 128)               // 16

__global__ __launch_bounds__(256) void attn_mma(
    const __nv_bfloat16* __restrict__ Qh, const __nv_bfloat16* __restrict__ Ql,
    const __nv_bfloat16* __restrict__ Kh, const __nv_bfloat16* __restrict__ Kl,
    const __nv_bfloat16* __restrict__ Vh, const __nv_bfloat16* __restrict__ Vl,
    __nv_bfloat16* __restrict__ ys)
{
    extern __shared__ char sm[];
    const uint32_t sb = smem_u32(sm);
    const int tid  = threadIdx.x;
    const int lane = tid & 31;
    const int wq   = tid >> 5;                 // 0..7
    const int bx   = blockIdx.x;
    const int qi   = (NQT - 1) - (bx >> 5);    // heavy tiles first
    const int bh   = bx & 31;
    const int b    = bh >> 4;
    const int h    = bh & 15;
    const size_t hoff = (size_t)bh * TT * HD;

    // Q tiles: 128 rows, hi+lo
#pragma unroll
    for (int j = 0; j < 4; j++) {
        int id = tid + 256 * j;   // 0..1023
        int r = id >> 3, c = id & 7;
        const size_t g = hoff + (size_t)(qi * 128 + r) * HD + c * 8;
        cp16(sb + Q_H + r * AP + c * 16, Qh + g);
        cp16(sb + Q_L + r * AP + c * 16, Ql + g);
    }
    CP_COMMIT();

    auto load_kv = [&](int kt, int st) {
        const uint32_t s0 = sb + QSTG + st * KV_STAGE;
        const int t0 = kt * 64;
#pragma unroll
        for (int j = 0; j < 2; j++) {
            int id = tid + 256 * j;   // 0..511
            int r = id >> 3, c = id & 7;
            const size_t g = hoff + (size_t)(t0 + r) * HD + c * 8;
            const uint32_t so = r * AP + c * 16;
            cp16(s0 + 0 * KTILE_B + so, Kh + g);
            cp16(s0 + 1 * KTILE_B + so, Kl + g);
            cp16(s0 + 2 * KTILE_B + so, Vh + g);
            cp16(s0 + 3 * KTILE_B + so, Vl + g);
        }
        CP_COMMIT();
    };

    load_kv(0, 0);
    CP_WAIT(0);
    __syncthreads();

    uint32_t qhf[4][4], qlf[4][4];
#pragma unroll
    for (int ks = 0; ks < 4; ks++) {
        uint32_t ao = (wq * 16 + (lane & 15)) * AP + (ks * 16 + (lane >> 4) * 8) * 2;
        ldsm4(qhf[ks], sb + Q_H + ao);
        ldsm4(qlf[ks], sb + Q_L + ao);
    }

    float oacc[8][4];
#pragma unroll
    for (int j = 0; j < 8; j++)
#pragma unroll
        for (int r = 0; r < 4; r++) oacc[j][r] = 0.0f;
    float m_a = -1e30f, m_b = -1e30f, l_a = 0.0f, l_b = 0.0f;

    const int wrow = qi * 128 + wq * 16;   // warp's first q row
    const int ntiles = 2 * qi + 2;

    for (int kt = 0; kt < ntiles; kt++) {
        const int st = kt & 1;
        if (kt + 1 < ntiles) load_kv(kt + 1, st ^ 1);

        const uint32_t s0 = sb + QSTG + st * KV_STAGE;

        if (kt * 64 <= wrow + 15) {   // warp has at least one unmasked row
            float sacc[8][4];
#pragma unroll
            for (int j = 0; j < 8; j++)
#pragma unroll
                for (int r = 0; r < 4; r++) sacc[j][r] = 0.0f;

#pragma unroll
            for (int ks = 0; ks < 4; ks++) {
#pragma unroll
                for (int jp = 0; jp < 4; jp++) {
                    uint32_t ro = ((2 * jp + ((lane >> 4) & 1)) * 8 + (lane & 7)) * AP
                                + (ks * 16 + ((lane >> 3) & 1) * 8) * 2;
                    uint32_t kbh[4], kbl[4];
                    ldsm4(kbh, s0 + 0 * KTILE_B + ro);
                    ldsm4(kbl, s0 + 1 * KTILE_B + ro);
                    mma16816(sacc[2 * jp],     qhf[ks], &kbh[0]);
                    mma16816(sacc[2 * jp],     qlf[ks], &kbh[0]);
                    mma16816(sacc[2 * jp],     qhf[ks], &kbl[0]);
                    mma16816(sacc[2 * jp + 1], qhf[ks], &kbh[2]);
                    mma16816(sacc[2 * jp + 1], qlf[ks], &kbh[2]);
                    mma16816(sacc[2 * jp + 1], qhf[ks], &kbl[2]);
                }
            }

            // causal mask near the diagonal (global indices)
            if (kt * 64 + 63 > wrow) {
                const int rA = wrow + (lane >> 2);
                const int rB = rA + 8;
#pragma unroll
                for (int j = 0; j < 8; j++) {
                    const int cl = kt * 64 + j * 8 + 2 * (lane & 3);
                    if (cl     > rA) sacc[j][0] = -1e30f;
                    if (cl + 1 > rA) sacc[j][1] = -1e30f;
                    if (cl     > rB) sacc[j][2] = -1e30f;
                    if (cl + 1 > rB) sacc[j][3] = -1e30f;
                }
            }

            float mx_a = -1e30f, mx_b = -1e30f;
#pragma unroll
            for (int j = 0; j < 8; j++) {
                mx_a = fmaxf(mx_a, fmaxf(sacc[j][0], sacc[j][1]));
                mx_b = fmaxf(mx_b, fmaxf(sacc[j][2], sacc[j][3]));
            }
            mx_a = fmaxf(mx_a, __shfl_xor_sync(0xffffffff, mx_a, 1));
            mx_a = fmaxf(mx_a, __shfl_xor_sync(0xffffffff, mx_a, 2));
            mx_b = fmaxf(mx_b, __shfl_xor_sync(0xffffffff, mx_b, 1));
            mx_b = fmaxf(mx_b, __shfl_xor_sync(0xffffffff, mx_b, 2));

            const float mn_a = fmaxf(m_a, mx_a);
            const float mn_b = fmaxf(m_b, mx_b);
            const float al_a = __expf(m_a - mn_a);
            const float al_b = __expf(m_b - mn_b);
            l_a *= al_a; l_b *= al_b;
            m_a = mn_a;  m_b = mn_b;
#pragma unroll
            for (int j = 0; j < 8; j++) {
                oacc[j][0] *= al_a; oacc[j][1] *= al_a;
                oacc[j][2] *= al_b; oacc[j][3] *= al_b;
            }

            uint32_t pha[8], phb[8], pla[8], plb[8];
#pragma unroll
            for (int j = 0; j < 8; j++) {
                float p0 = __expf(sacc[j][0] - mn_a);
                float p1 = __expf(sacc[j][1] - mn_a);
                float p2 = __expf(sacc[j][2] - mn_b);
                float p3 = __expf(sacc[j][3] - mn_b);
                l_a += p0 + p1;
                l_b += p2 + p3;
                __nv_bfloat16 h0, l0, h1, l1, h2, l2, h3, l3;
                split1(p0, h0, l0); split1(p1, h1, l1);
                split1(p2, h2, l2); split1(p3, h3, l3);
                pha[j] = pack_bf16x2(h0, h1);
                phb[j] = pack_bf16x2(h2, h3);
                pla[j] = pack_bf16x2(l0, l1);
                plb[j] = pack_bf16x2(l2, l3);
            }

#pragma unroll
            for (int ks = 0; ks < 4; ks++) {
                uint32_t Ah[4] = {pha[2 * ks], phb[2 * ks], pha[2 * ks + 1], phb[2 * ks + 1]};
                uint32_t Al[4] = {pla[2 * ks], plb[2 * ks], pla[2 * ks + 1], plb[2 * ks + 1]};
#pragma unroll
                for (int dp = 0; dp < 4; dp++) {
                    uint32_t vo = (ks * 16 + (lane & 15)) * AP
                                + (dp * 16 + ((lane >> 4) & 1) * 8) * 2;
                    uint32_t vbh[4], vbl[4];
                    ldsm4t(vbh, s0 + 2 * KTILE_B + vo);
                    ldsm4t(vbl, s0 + 3 * KTILE_B + vo);
                    mma16816(oacc[2 * dp],     Ah, &vbh[0]);
                    mma16816(oacc[2 * dp],     Al, &vbh[0]);
                    mma16816(oacc[2 * dp],     Ah, &vbl[0]);
                    mma16816(oacc[2 * dp + 1], Ah, &vbh[2]);
                    mma16816(oacc[2 * dp + 1], Al, &vbh[2]);
                    mma16816(oacc[2 * dp + 1], Ah, &vbl[2]);
                }
            }
        }

        if (kt + 1 < ntiles) { CP_WAIT(0); }
        __syncthreads();
    }

    l_a += __shfl_xor_sync(0xffffffff, l_a, 1);
    l_a += __shfl_xor_sync(0xffffffff, l_a, 2);
    l_b += __shfl_xor_sync(0xffffffff, l_b, 1);
    l_b += __shfl_xor_sync(0xffffffff, l_b, 2);
    const float inv_a = 1.0f / l_a;
    const float inv_b = 1.0f / l_b;

    const int tA = wrow + (lane >> 2);
    const int tB = tA + 8;
    const size_t rowA = (size_t)(b * TT + tA) * K3;
    const size_t rowB = (size_t)(b * TT + tB) * K3;
#pragma unroll
    for (int j = 0; j < 8; j++) {
        const int d = h * HD + j * 8 + 2 * (lane & 3);
        float2 vA = make_float2(oacc[j][0] * inv_a, oacc[j][1] * inv_a);
        float2 vB = make_float2(oacc[j][2] * inv_b, oacc[j][3] * inv_b);
        __nv_bfloat16 hA0, lA0, hA1, lA1, hB0, lB0, hB1, lB1;
        split1(vA.x, hA0, lA0); split1(vA.y, hA1, lA1);
        split1(vB.x, hB0, lB0); split1(vB.y, hB1, lB1);
        uint32_t hpA = pack_bf16x2(hA0, hA1), lpA = pack_bf16x2(lA0, lA1);
        uint32_t hpB = pack_bf16x2(hB0, hB1), lpB = pack_bf16x2(lB0, lB1);
        *reinterpret_cast<uint32_t*>(ys + rowA + d)          = hpA;
        *reinterpret_cast<uint32_t*>(ys + rowA + CC + d)     = hpA;
        *reinterpret_cast<uint32_t*>(ys + rowA + 2 * CC + d) = lpA;
        *reinterpret_cast<uint32_t*>(ys + rowB + d)          = hpB;
        *reinterpret_cast<uint32_t*>(ys + rowB + CC + d)     = hpB;
        *reinterpret_cast<uint32_t*>(ys + rowB + 2 * CC + d) = lpB;
    }
}

// ---------------------------------------------------------------------------
extern "C" void kernel_launch(void* const* d_in, const int* in_sizes, int n_in,
                              void* d_out, int out_size)
{
    const float* x     = (const float*)d_in[0];
    const float* w_qkv = (const float*)d_in[1];
    const float* b_qkv = (const float*)d_in[2];
    const float* w_out = (const float*)d_in[3];
    const float* b_out = (const float*)d_in[4];
    float* out = (float*)d_out;

    __nv_bfloat16 *xs, *ys, *wqs, *wos, *qh, *ql, *kh, *kl, *vh, *vl;
    cudaGetSymbolAddress((void**)&xs,  g_xs);
    cudaGetSymbolAddress((void**)&ys,  g_ys);
    cudaGetSymbolAddress((void**)&wqs, g_wqs);
    cudaGetSymbolAddress((void**)&wos, g_wos);
    cudaGetSymbolAddress((void**)&qh,  g_qh);
    cudaGetSymbolAddress((void**)&ql,  g_ql);
    cudaGetSymbolAddress((void**)&kh,  g_kh);
    cudaGetSymbolAddress((void**)&kl,  g_kl);
    cudaGetSymbolAddress((void**)&vh,  g_vh);
    cudaGetSymbolAddress((void**)&vl,  g_vl);

    cudaFuncSetAttribute(gemm_mma<0>, cudaFuncAttributeMaxDynamicSharedMemorySize, GEMM_SMEM);
    cudaFuncSetAttribute(gemm_mma<1>, cudaFuncAttributeMaxDynamicSharedMemorySize, GEMM_SMEM);
    cudaFuncSetAttribute(attn_mma, cudaFuncAttributeMaxDynamicSharedMemorySize, ATTN_SMEM);

    // Input conversions
    {
        int n4 = M_ROWS * CC / 4;
        split3_act<<<(n4 + 255) / 256, 256>>>(x, xs, n4);
        dim3 g1(QKV_N / 32, CC / 32);
        tsplit3<<<g1, 256>>>(w_qkv, QKV_N, wqs);
        dim3 g2(CC / 32, CC / 32);
        tsplit3<<<g2, 256>>>(w_out, CC, wos);
    }

    // 1) QKV GEMM, epilogue writes head-major split q/k/v directly
    {
        dim3 grid(QKV_N / 128, M_ROWS / 128);
        gemm_mma<1><<<grid, 256, GEMM_SMEM>>>(QKV_N, xs, wqs, b_qkv, nullptr,
                                              qh, ql, kh, kl, vh, vl);
    }

    // 2) flash attention -> ys (split3 layout)
    {
        attn_mma<<<BB * HH * NQT, 256, ATTN_SMEM>>>(qh, ql, kh, kl, vh, vl, ys);
    }

    // 3) out = y @ w_out + b_out
    {
        dim3 grid(CC / 128, M_ROWS / 128);
        gemm_mma<0><<<grid, 256, GEMM_SMEM>>>(CC, ys, wos, b_out, out,
                                              nullptr, nullptr, nullptr, nullptr, nullptr, nullptr);
    }
}

// round 14
// speedup vs baseline: 1.0695x; 1.0695x over previous
#include <cuda_runtime.h>
#include <cuda_bf16.h>
#include <math.h>
#include <stdint.h>

// Problem constants
#define BB 2
#define TT 2048
#define CC 1024
#define HH 16
#define HD 64
#define M_ROWS (BB*TT)        // 4096
#define QKV_N  (3*CC)         // 3072
#define K3     (3*CC)         // augmented K = 3072

// ---------------------------------------------------------------------------
// Scratch (__device__ globals; no cudaMalloc allowed)
// ---------------------------------------------------------------------------
__device__ __nv_bfloat16 g_xs [(size_t)M_ROWS * K3];
__device__ __nv_bfloat16 g_ys [(size_t)M_ROWS * K3];
__device__ __nv_bfloat16 g_wqs[(size_t)QKV_N * K3];
__device__ __nv_bfloat16 g_wos[(size_t)CC * K3];
#define HSZ ((size_t)BB * HH * TT * HD)
__device__ __nv_bfloat16 g_qh[HSZ];
__device__ __nv_bfloat16 g_ql[HSZ];
__device__ __nv_bfloat16 g_kh[HSZ];
__device__ __nv_bfloat16 g_kl[HSZ];
__device__ __nv_bfloat16 g_vh[HSZ];
__device__ __nv_bfloat16 g_vl[HSZ];

// ---------------------------------------------------------------------------
// PTX helpers
// ---------------------------------------------------------------------------
__device__ __forceinline__ uint32_t smem_u32(const void* p) {
    uint32_t a;
    asm("{ .reg .u64 t; cvta.to.shared.u64 t, %1; cvt.u32.u64 %0, t; }" : "=r"(a) : "l"(p));
    return a;
}
__device__ __forceinline__ void cp16(uint32_t dst, const void* src) {
    asm volatile("cp.async.cg.shared.global [%0], [%1], 16;" :: "r"(dst), "l"(src));
}
#define CP_COMMIT() asm volatile("cp.async.commit_group;" ::: "memory")
#define CP_WAIT(n)  asm volatile("cp.async.wait_group %0;" :: "n"(n) : "memory")

__device__ __forceinline__ void ldsm4(uint32_t* r, uint32_t addr) {
    asm volatile("ldmatrix.sync.aligned.m8n8.x4.shared.b16 {%0,%1,%2,%3}, [%4];"
        : "=r"(r[0]), "=r"(r[1]), "=r"(r[2]), "=r"(r[3]) : "r"(addr));
}
__device__ __forceinline__ void ldsm4t(uint32_t* r, uint32_t addr) {
    asm volatile("ldmatrix.sync.aligned.m8n8.x4.trans.shared.b16 {%0,%1,%2,%3}, [%4];"
        : "=r"(r[0]), "=r"(r[1]), "=r"(r[2]), "=r"(r[3]) : "r"(addr));
}
__device__ __forceinline__ void mma16816(float* d, const uint32_t* a, const uint32_t* b) {
    asm volatile(
        "mma.sync.aligned.m16n8k16.row.col.f32.bf16.bf16.f32 "
        "{%0,%1,%2,%3}, {%4,%5,%6,%7}, {%8,%9}, {%0,%1,%2,%3};"
        : "+f"(d[0]), "+f"(d[1]), "+f"(d[2]), "+f"(d[3])
        : "r"(a[0]), "r"(a[1]), "r"(a[2]), "r"(a[3]), "r"(b[0]), "r"(b[1]));
}
__device__ __forceinline__ uint32_t pack_bf16x2(__nv_bfloat16 a, __nv_bfloat16 b) {
    __nv_bfloat162 h = __halves2bfloat162(a, b);
    return *reinterpret_cast<uint32_t*>(&h);
}
__device__ __forceinline__ void split1(float v, __nv_bfloat16& h, __nv_bfloat16& l) {
    h = __float2bfloat16(v);
    l = __float2bfloat16(v - __bfloat162float(h));
}

// ---------------------------------------------------------------------------
// Conversion kernels for the GEMM inputs
// ---------------------------------------------------------------------------
__global__ void split3_act(const float* __restrict__ in,
                           __nv_bfloat16* __restrict__ out, int n4)
{
    int i = blockIdx.x * blockDim.x + threadIdx.x;
    if (i >= n4) return;
    int m  = i >> 8;
    int kc = i & 255;
    float4 v = reinterpret_cast<const float4*>(in)[i];
    __nv_bfloat16 h[4], l[4];
    float f[4] = {v.x, v.y, v.z, v.w};
#pragma unroll
    for (int j = 0; j < 4; j++) split1(f[j], h[j], l[j]);
    __nv_bfloat162 hp0(h[0], h[1]), hp1(h[2], h[3]);
    __nv_bfloat162 lp0(l[0], l[1]), lp1(l[2], l[3]);
    __nv_bfloat162* o = reinterpret_cast<__nv_bfloat162*>(out + (size_t)m * K3 + kc * 4);
    o[0] = hp0; o[1] = hp1;
    o[CC / 2 + 0] = hp0; o[CC / 2 + 1] = hp1;
    o[CC + 0] = lp0; o[CC + 1] = lp1;
}

__global__ __launch_bounds__(256) void tsplit3(
    const float* __restrict__ W, int N, __nv_bfloat16* __restrict__ out)
{
    __shared__ float t[32][33];
    const int nb = blockIdx.x * 32;
    const int kb = blockIdx.y * 32;
    const int tx = threadIdx.x & 31;
    const int ty = threadIdx.x >> 5;
    for (int r = ty; r < 32; r += 8)
        t[r][tx] = W[(size_t)(kb + r) * N + nb + tx];
    __syncthreads();
    for (int r = ty; r < 32; r += 8) {
        float v = t[tx][r];
        __nv_bfloat16 h, l;
        split1(v, h, l);
        size_t o = (size_t)(nb + r) * K3 + kb + tx;
        out[o]          = h;
        out[o + CC]     = l;
        out[o + 2 * CC] = h;
    }
}

// ---------------------------------------------------------------------------
// bf16 HMMA GEMM: C[M,N] = A'[M,3K] @ B'[N,3K]^T + bias[N]
// 128x128 CTA tile, BK=64, 4 warps (2x2) with 64x64 warp tiles (MMA:LDSM = 4),
// 3-stage cp.async ring (R8 loop order), swizzled 128B-row smem, inline
// fragment addressing (R8 style).
// ---------------------------------------------------------------------------
#define GATILE 16384             // 128 rows * 128 B
#define GSTAGE (2 * GATILE)      // 32768 (A + B)
#define GEMM_SMEM (3 * GSTAGE)   // 98304
#define NKB (K3 / 64)            // 48

template <int MODE>
__global__ __launch_bounds__(128) void gemm_mma(
    int N,
    const __nv_bfloat16* __restrict__ A,
    const __nv_bfloat16* __restrict__ B,
    const float* __restrict__ bias,
    float* __restrict__ C,
    __nv_bfloat16* __restrict__ qh, __nv_bfloat16* __restrict__ ql,
    __nv_bfloat16* __restrict__ kh, __nv_bfloat16* __restrict__ kl,
    __nv_bfloat16* __restrict__ vh, __nv_bfloat16* __restrict__ vl)
{
    extern __shared__ char smem[];
    const uint32_t sbase = smem_u32(smem);

    const int tid  = threadIdx.x;
    const int lane = tid & 31;
    const int wid  = tid >> 5;         // 0..3
    const int wm   = wid >> 1;         // 0..1
    const int wn   = wid & 1;          // 0..1
    const int m0   = blockIdx.y * 128;
    const int n0   = blockIdx.x * 128;

    // Loader: 128 threads, each owns rows lr+16j (j=0..7) at 16B unit lc.
    const int lr = tid >> 3;           // 0..15
    const int lc = tid & 7;            // 0..7
    const uint32_t stoff = (uint32_t)(lr * 128 + ((lc ^ (lr & 7)) * 16));
    const __nv_bfloat16* pA = A + (size_t)(m0 + lr) * K3 + lc * 8;
    const __nv_bfloat16* pB = B + (size_t)(n0 + lr) * K3 + lc * 8;

    float acc[4][8][4];
#pragma unroll
    for (int mi = 0; mi < 4; mi++)
#pragma unroll
        for (int nj = 0; nj < 8; nj++)
#pragma unroll
            for (int r = 0; r < 4; r++) acc[mi][nj][r] = 0.0f;

    auto load_stage = [&](int kb, int st) {
        const uint32_t sa  = sbase + st * GSTAGE;
        const uint32_t sbm = sa + GATILE;
        const int k0 = kb * 64;
#pragma unroll
        for (int j = 0; j < 8; j++)
            cp16(sa + stoff + j * 2048, pA + (size_t)j * 16 * K3 + k0);
#pragma unroll
        for (int j = 0; j < 8; j++)
            cp16(sbm + stoff + j * 2048, pB + (size_t)j * 16 * K3 + k0);
        CP_COMMIT();
    };

    load_stage(0, 0);
    load_stage(1, 1);

    for (int kb = 0; kb < NKB; kb++) {
        const int st = kb % 3;
        if (kb + 2 < NKB) {
            load_stage(kb + 2, (kb + 2) % 3);
            CP_WAIT(2);
        } else if (kb + 1 < NKB) {
            CP_WAIT(1);
        } else {
            CP_WAIT(0);
        }
        __syncthreads();

        const uint32_t sa  = sbase + st * GSTAGE;
        const uint32_t sbm = sa + GATILE;

#pragma unroll
        for (int ks = 0; ks < 4; ks++) {
            uint32_t af[4][4];
#pragma unroll
            for (int mi = 0; mi < 4; mi++) {
                const int r = wm * 64 + mi * 16 + (lane & 15);
                const int u = (ks * 2 + (lane >> 4)) ^ (r & 7);
                ldsm4(af[mi], sa + r * 128 + u * 16);
            }
            uint32_t bf[4][4];
#pragma unroll
            for (int nj2 = 0; nj2 < 4; nj2++) {
                const int r = wn * 64 + nj2 * 16 + (lane & 7) + (((lane >> 4) & 1) * 8);
                const int u = (ks * 2 + ((lane >> 3) & 1)) ^ (r & 7);
                ldsm4(bf[nj2], sbm + r * 128 + u * 16);
            }
#pragma unroll
            for (int mi = 0; mi < 4; mi++)
#pragma unroll
                for (int nj = 0; nj < 8; nj++)
                    mma16816(acc[mi][nj], af[mi], &bf[nj >> 1][(nj & 1) * 2]);
        }
        __syncthreads();
    }

    // Epilogue
#pragma unroll
    for (int mi = 0; mi < 4; mi++) {
#pragma unroll
        for (int nj = 0; nj < 8; nj++) {
            const int row = m0 + wm * 64 + mi * 16 + (lane >> 2);
            const int col = n0 + wn * 64 + nj * 8 + 2 * (lane & 3);
            float2 bz = *reinterpret_cast<const float2*>(bias + col);
            float2 v0 = make_float2(acc[mi][nj][0] + bz.x, acc[mi][nj][1] + bz.y);
            float2 v1 = make_float2(acc[mi][nj][2] + bz.x, acc[mi][nj][3] + bz.y);
            if (MODE == 0) {
                *reinterpret_cast<float2*>(C + (size_t)row * N + col) = v0;
                *reinterpret_cast<float2*>(C + (size_t)(row + 8) * N + col) = v1;
            } else {
                const int seg = col >> 10;       // 0=q 1=k 2=v
                const int hc  = col & 1023;
                const int h   = hc >> 6;
                const int d   = hc & 63;
                if (seg == 0) { v0.x *= 0.125f; v0.y *= 0.125f; v1.x *= 0.125f; v1.y *= 0.125f; }
                __nv_bfloat16* hp = (seg == 0) ? qh : (seg == 1) ? kh : vh;
                __nv_bfloat16* lp = (seg == 0) ? ql : (seg == 1) ? kl : vl;
#pragma unroll
                for (int rr = 0; rr < 2; rr++) {
                    const int m = row + rr * 8;
                    const int b = m >> 11, t = m & 2047;
                    const size_t dst = (((size_t)(b * HH + h)) * TT + t) * HD + d;
                    float2 v = rr ? v1 : v0;
                    __nv_bfloat16 h0, l0, h1, l1;
                    split1(v.x, h0, l0);
                    split1(v.y, h1, l1);
                    *reinterpret_cast<uint32_t*>(hp + dst) = pack_bf16x2(h0, h1);
                    *reinterpret_cast<uint32_t*>(lp + dst) = pack_bf16x2(l0, l1);
                }
            }
        }
    }
}

// ---------------------------------------------------------------------------
// Flash attention on HMMA, split-bf16 (3-term) — exact R8 version (best).
// 128 threads (4 warps), Q tile 64, KV tiles 64, double-buffered.
// Epilogue writes split3 rows of y directly: [yh | yh | yl].
// ---------------------------------------------------------------------------
#define AP 144
#define ATILE_B (64 * AP)
#define Q_H 0
#define Q_L ATILE_B
#define STG (2 * ATILE_B)
#define KV_STAGE (4 * ATILE_B)
#define ATTN_SMEM (STG + 2 * KV_STAGE)
#define NQT (TT / 64)

__global__ __launch_bounds__(128) void attn_mma(
    const __nv_bfloat16* __restrict__ Qh, const __nv_bfloat16* __restrict__ Ql,
    const __nv_bfloat16* __restrict__ Kh, const __nv_bfloat16* __restrict__ Kl,
    const __nv_bfloat16* __restrict__ Vh, const __nv_bfloat16* __restrict__ Vl,
    __nv_bfloat16* __restrict__ ys)
{
    extern __shared__ char sm[];
    const uint32_t sb = smem_u32(sm);
    const int tid  = threadIdx.x;
    const int lane = tid & 31;
    const int wq   = tid >> 5;
    const int bx   = blockIdx.x;
    const int qi   = (NQT - 1) - (bx >> 5);
    const int bh   = bx & 31;
    const int b    = bh >> 4;
    const int h    = bh & 15;
    const size_t hoff = (size_t)bh * TT * HD;

#pragma unroll
    for (int j = 0; j < 4; j++) {
        int id = tid + 128 * j;
        int r = id >> 3, c = id & 7;
        const size_t g = hoff + (size_t)(qi * 64 + r) * HD + c * 8;
        cp16(sb + Q_H + r * AP + c * 16, Qh + g);
        cp16(sb + Q_L + r * AP + c * 16, Ql + g);
    }
    CP_COMMIT();

    auto load_kv = [&](int kt, int st) {
        const uint32_t s0 = sb + STG + st * KV_STAGE;
        const int t0 = kt * 64;
#pragma unroll
        for (int j = 0; j < 4; j++) {
            int id = tid + 128 * j;
            int r = id >> 3, c = id & 7;
            const size_t g = hoff + (size_t)(t0 + r) * HD + c * 8;
            const uint32_t so = r * AP + c * 16;
            cp16(s0 + 0 * ATILE_B + so, Kh + g);
            cp16(s0 + 1 * ATILE_B + so, Kl + g);
            cp16(s0 + 2 * ATILE_B + so, Vh + g);
            cp16(s0 + 3 * ATILE_B + so, Vl + g);
        }
        CP_COMMIT();
    };

    load_kv(0, 0);
    CP_WAIT(0);
    __syncthreads();

    uint32_t qhf[4][4], qlf[4][4];
#pragma unroll
    for (int ks = 0; ks < 4; ks++) {
        uint32_t ao = (wq * 16 + (lane & 15)) * AP + (ks * 16 + (lane >> 4) * 8) * 2;
        ldsm4(qhf[ks], sb + Q_H + ao);
        ldsm4(qlf[ks], sb + Q_L + ao);
    }

    float oacc[8][4];
#pragma unroll
    for (int j = 0; j < 8; j++)
#pragma unroll
        for (int r = 0; r < 4; r++) oacc[j][r] = 0.0f;
    float m_a = -1e30f, m_b = -1e30f, l_a = 0.0f, l_b = 0.0f;

    for (int kt = 0; kt <= qi; kt++) {
        const int st = kt & 1;
        if (kt < qi) load_kv(kt + 1, st ^ 1);

        const uint32_t s0 = sb + STG + st * KV_STAGE;

        float sacc[8][4];
#pragma unroll
        for (int j = 0; j < 8; j++)
#pragma unroll
            for (int r = 0; r < 4; r++) sacc[j][r] = 0.0f;

#pragma unroll
        for (int ks = 0; ks < 4; ks++) {
#pragma unroll
            for (int jp = 0; jp < 4; jp++) {
                uint32_t ro = ((2 * jp + ((lane >> 4) & 1)) * 8 + (lane & 7)) * AP
                            + (ks * 16 + ((lane >> 3) & 1) * 8) * 2;
                uint32_t kbh[4], kbl[4];
                ldsm4(kbh, s0 + 0 * ATILE_B + ro);
                ldsm4(kbl, s0 + 1 * ATILE_B + ro);
                mma16816(sacc[2 * jp],     qhf[ks], &kbh[0]);
                mma16816(sacc[2 * jp],     qlf[ks], &kbh[0]);
                mma16816(sacc[2 * jp],     qhf[ks], &kbl[0]);
                mma16816(sacc[2 * jp + 1], qhf[ks], &kbh[2]);
                mma16816(sacc[2 * jp + 1], qlf[ks], &kbh[2]);
                mma16816(sacc[2 * jp + 1], qhf[ks], &kbl[2]);
            }
        }

        if (kt == qi) {
            const int rA = wq * 16 + (lane >> 2);
            const int rB = rA + 8;
#pragma unroll
            for (int j = 0; j < 8; j++) {
                const int cl = j * 8 + 2 * (lane & 3);
                if (cl     > rA) sacc[j][0] = -1e30f;
                if (cl + 1 > rA) sacc[j][1] = -1e30f;
                if (cl     > rB) sacc[j][2] = -1e30f;
                if (cl + 1 > rB) sacc[j][3] = -1e30f;
            }
        }

        float mx_a = -1e30f, mx_b = -1e30f;
#pragma unroll
        for (int j = 0; j < 8; j++) {
            mx_a = fmaxf(mx_a, fmaxf(sacc[j][0], sacc[j][1]));
            mx_b = fmaxf(mx_b, fmaxf(sacc[j][2], sacc[j][3]));
        }
        mx_a = fmaxf(mx_a, __shfl_xor_sync(0xffffffff, mx_a, 1));
        mx_a = fmaxf(mx_a, __shfl_xor_sync(0xffffffff, mx_a, 2));
        mx_b = fmaxf(mx_b, __shfl_xor_sync(0xffffffff, mx_b, 1));
        mx_b = fmaxf(mx_b, __shfl_xor_sync(0xffffffff, mx_b, 2));

        const float mn_a = fmaxf(m_a, mx_a);
        const float mn_b = fmaxf(m_b, mx_b);
        const float al_a = __expf(m_a - mn_a);
        const float al_b = __expf(m_b - mn_b);
        l_a *= al_a; l_b *= al_b;
        m_a = mn_a;  m_b = mn_b;
#pragma unroll
        for (int j = 0; j < 8; j++) {
            oacc[j][0] *= al_a; oacc[j][1] *= al_a;
            oacc[j][2] *= al_b; oacc[j][3] *= al_b;
        }

        uint32_t pha[8], phb[8], pla[8], plb[8];
#pragma unroll
        for (int j = 0; j < 8; j++) {
            float p0 = __expf(sacc[j][0] - mn_a);
            float p1 = __expf(sacc[j][1] - mn_a);
            float p2 = __expf(sacc[j][2] - mn_b);
            float p3 = __expf(sacc[j][3] - mn_b);
            l_a += p0 + p1;
            l_b += p2 + p3;
            __nv_bfloat16 h0, l0, h1, l1, h2, l2, h3, l3;
            split1(p0, h0, l0); split1(p1, h1, l1);
            split1(p2, h2, l2); split1(p3, h3, l3);
            pha[j] = pack_bf16x2(h0, h1);
            phb[j] = pack_bf16x2(h2, h3);
            pla[j] = pack_bf16x2(l0, l1);
            plb[j] = pack_bf16x2(l2, l3);
        }

#pragma unroll
        for (int ks = 0; ks < 4; ks++) {
            uint32_t Ah[4] = {pha[2 * ks], phb[2 * ks], pha[2 * ks + 1], phb[2 * ks + 1]};
            uint32_t Al[4] = {pla[2 * ks], plb[2 * ks], pla[2 * ks + 1], plb[2 * ks + 1]};
#pragma unroll
            for (int dp = 0; dp < 4; dp++) {
                uint32_t vo = (ks * 16 + (lane & 15)) * AP
                            + (dp * 16 + ((lane >> 4) & 1) * 8) * 2;
                uint32_t vbh[4], vbl[4];
                ldsm4t(vbh, s0 + 2 * ATILE_B + vo);
                ldsm4t(vbl, s0 + 3 * ATILE_B + vo);
                mma16816(oacc[2 * dp],     Ah, &vbh[0]);
                mma16816(oacc[2 * dp],     Al, &vbh[0]);
                mma16816(oacc[2 * dp],     Ah, &vbl[0]);
                mma16816(oacc[2 * dp + 1], Ah, &vbh[2]);
                mma16816(oacc[2 * dp + 1], Al, &vbh[2]);
                mma16816(oacc[2 * dp + 1], Ah, &vbl[2]);
            }
        }

        if (kt < qi) { CP_WAIT(0); }
        __syncthreads();
    }

    l_a += __shfl_xor_sync(0xffffffff, l_a, 1);
    l_a += __shfl_xor_sync(0xffffffff, l_a, 2);
    l_b += __shfl_xor_sync(0xffffffff, l_b, 1);
    l_b += __shfl_xor_sync(0xffffffff, l_b, 2);
    const float inv_a = 1.0f / l_a;
    const float inv_b = 1.0f / l_b;

    const int tA = qi * 64 + wq * 16 + (lane >> 2);
    const int tB = tA + 8;
    const size_t rowA = (size_t)(b * TT + tA) * K3;
    const size_t rowB = (size_t)(b * TT + tB) * K3;
#pragma unroll
    for (int j = 0; j < 8; j++) {
        const int d = h * HD + j * 8 + 2 * (lane & 3);
        float2 vA = make_float2(oacc[j][0] * inv_a, oacc[j][1] * inv_a);
        float2 vB = make_float2(oacc[j][2] * inv_b, oacc[j][3] * inv_b);
        __nv_bfloat16 hA0, lA0, hA1, lA1, hB0, lB0, hB1, lB1;
        split1(vA.x, hA0, lA0); split1(vA.y, hA1, lA1);
        split1(vB.x, hB0, lB0); split1(vB.y, hB1, lB1);
        uint32_t hpA = pack_bf16x2(hA0, hA1), lpA = pack_bf16x2(lA0, lA1);
        uint32_t hpB = pack_bf16x2(hB0, hB1), lpB = pack_bf16x2(lB0, lB1);
        *reinterpret_cast<uint32_t*>(ys + rowA + d)          = hpA;
        *reinterpret_cast<uint32_t*>(ys + rowA + CC + d)     = hpA;
        *reinterpret_cast<uint32_t*>(ys + rowA + 2 * CC + d) = lpA;
        *reinterpret_cast<uint32_t*>(ys + rowB + d)          = hpB;
        *reinterpret_cast<uint32_t*>(ys + rowB + CC + d)     = hpB;
        *reinterpret_cast<uint32_t*>(ys + rowB + 2 * CC + d) = lpB;
    }
}

// ---------------------------------------------------------------------------
extern "C" void kernel_launch(void* const* d_in, const int* in_sizes, int n_in,
                              void* d_out, int out_size)
{
    const float* x     = (const float*)d_in[0];
    const float* w_qkv = (const float*)d_in[1];
    const float* b_qkv = (const float*)d_in[2];
    const float* w_out = (const float*)d_in[3];
    const float* b_out = (const float*)d_in[4];
    float* out = (float*)d_out;

    __nv_bfloat16 *xs, *ys, *wqs, *wos, *qh, *ql, *kh, *kl, *vh, *vl;
    cudaGetSymbolAddress((void**)&xs,  g_xs);
    cudaGetSymbolAddress((void**)&ys,  g_ys);
    cudaGetSymbolAddress((void**)&wqs, g_wqs);
    cudaGetSymbolAddress((void**)&wos, g_wos);
    cudaGetSymbolAddress((void**)&qh,  g_qh);
    cudaGetSymbolAddress((void**)&ql,  g_ql);
    cudaGetSymbolAddress((void**)&kh,  g_kh);
    cudaGetSymbolAddress((void**)&kl,  g_kl);
    cudaGetSymbolAddress((void**)&vh,  g_vh);
    cudaGetSymbolAddress((void**)&vl,  g_vl);

    cudaFuncSetAttribute(gemm_mma<0>, cudaFuncAttributeMaxDynamicSharedMemorySize, GEMM_SMEM);
    cudaFuncSetAttribute(gemm_mma<1>, cudaFuncAttributeMaxDynamicSharedMemorySize, GEMM_SMEM);
    cudaFuncSetAttribute(attn_mma, cudaFuncAttributeMaxDynamicSharedMemorySize, ATTN_SMEM);

    // Input conversions
    {
        int n4 = M_ROWS * CC / 4;
        split3_act<<<(n4 + 255) / 256, 256>>>(x, xs, n4);
        dim3 g1(QKV_N / 32, CC / 32);
        tsplit3<<<g1, 256>>>(w_qkv, QKV_N, wqs);
        dim3 g2(CC / 32, CC / 32);
        tsplit3<<<g2, 256>>>(w_out, CC, wos);
    }

    // 1) QKV GEMM, epilogue writes head-major split q/k/v directly
    {
        dim3 grid(QKV_N / 128, M_ROWS / 128);
        gemm_mma<1><<<grid, 128, GEMM_SMEM>>>(QKV_N, xs, wqs, b_qkv, nullptr,
                                              qh, ql, kh, kl, vh, vl);
    }

    // 2) flash attention -> ys (split3 layout)
    {
        attn_mma<<<BB * HH * NQT, 128, ATTN_SMEM>>>(qh, ql, kh, kl, vh, vl, ys);
    }

    // 3) out = y @ w_out + b_out
    {
        dim3 grid(CC / 128, M_ROWS / 128);
        gemm_mma<0><<<grid, 128, GEMM_SMEM>>>(CC, ys, wos, b_out, out,
                                              nullptr, nullptr, nullptr, nullptr, nullptr, nullptr);
    }
}